// round 11
// baseline (speedup 1.0000x reference)
#include <cuda_runtime.h>
#include <math.h>
#include <stdint.h>

#define BDIM 4096
#define RDIM 64
#define DDIM 512
#define BB   32                 // batch rows per CTA
#define NBLOCK (BDIM / BB)      // 128 CTAs
#define NTHREADS 256
#define ROWF 528                // padded row stride (floats); (528/4) mod 8 == 4 -> conflict-free LDS.128
#define W_TILE_F (BB * ROWF)    // 16896
#define E_TILE_F (RDIM * ROWF)  // 33792
#define DYN_SMEM ((W_TILE_F + E_TILE_F) * 4)   // 202752 B

__device__ float g_partial[NBLOCK];
__device__ int   g_count = 0;

__device__ __forceinline__ uint32_t smem_u32(const void* p) {
    return (uint32_t)__cvta_generic_to_shared(p);
}
__device__ __forceinline__ void bulk_cp(uint32_t dst, const void* src,
                                        uint32_t bytes, uint32_t mbar) {
    asm volatile(
        "cp.async.bulk.shared::cta.global.mbarrier::complete_tx::bytes [%0], [%1], %2, [%3];"
        :: "r"(dst), "l"(src), "r"(bytes), "r"(mbar) : "memory");
}
__device__ __forceinline__ void mbar_init(uint32_t mbar, uint32_t cnt) {
    asm volatile("mbarrier.init.shared.b64 [%0], %1;" :: "r"(mbar), "r"(cnt) : "memory");
}
__device__ __forceinline__ void mbar_expect_tx(uint32_t mbar, uint32_t bytes) {
    asm volatile("mbarrier.arrive.expect_tx.shared.b64 _, [%0], %1;"
                 :: "r"(mbar), "r"(bytes) : "memory");
}
__device__ __forceinline__ void mbar_wait(uint32_t mbar, uint32_t parity) {
    asm volatile(
        "{\n\t.reg .pred P;\n\t"
        "WL_%=:\n\t"
        "mbarrier.try_wait.parity.acquire.cta.shared::cta.b64 P, [%0], %1, 0x989680;\n\t"
        "@P bra.uni WD_%=;\n\t"
        "bra.uni WL_%=;\n\t"
        "WD_%=:\n\t}"
        :: "r"(mbar), "r"(parity) : "memory");
}
// split fp32 into tf32-exact hi + residual lo (bit patterns for mma)
__device__ __forceinline__ void split_u(float x, uint32_t& hi, uint32_t& lo) {
    uint32_t xb = __float_as_uint(x);
    hi = xb & 0xFFFFE000u;
    lo = __float_as_uint(x - __uint_as_float(hi));
}
__device__ __forceinline__ void mma_tf32(float* c, const uint32_t* a,
                                         uint32_t b0, uint32_t b1) {
    asm volatile(
        "mma.sync.aligned.m16n8k8.row.col.f32.tf32.tf32.f32 "
        "{%0,%1,%2,%3}, {%4,%5,%6,%7}, {%8,%9}, {%0,%1,%2,%3};"
        : "+f"(c[0]), "+f"(c[1]), "+f"(c[2]), "+f"(c[3])
        : "r"(a[0]), "r"(a[1]), "r"(a[2]), "r"(a[3]), "r"(b0), "r"(b1));
}

__global__ __launch_bounds__(NTHREADS, 1)
void fused_kernel(const float* __restrict__ w,
                  const float* __restrict__ e,
                  const float* __restrict__ label,
                  float* __restrict__ out, int out_size)
{
    extern __shared__ __align__(16) float dyn[];
    float* w_s = dyn;                 // [BB][ROWF]
    float* e_s = dyn + W_TILE_F;      // [RDIM][ROWF]

    __shared__ __align__(8) uint64_t mbar_sto;
    __shared__ float s_s[BB][65];     // dot products [b][r]
    __shared__ float ne_red[RDIM][4];
    __shared__ float ne_s[RDIM];
    __shared__ float nw_red[BB][9];
    __shared__ int   idx1_s[BB];
    __shared__ float fs[NBLOCK];
    __shared__ int   is_last;

    const int tid  = threadIdx.x;
    const int lane = tid & 31;
    const int wid  = tid >> 5;
    const int b0   = blockIdx.x * BB;
    const uint32_t mbar = smem_u32(&mbar_sto);

    // ---- stage w tile (32 rows) + e (64 rows) via bulk async copy ----
    if (tid == 0) mbar_init(mbar, 1);
    __syncthreads();
    if (tid == 0) mbar_expect_tx(mbar, (BB + RDIM) * DDIM * 4);
    __syncthreads();
    if (tid < BB) {
        bulk_cp(smem_u32(w_s + tid * ROWF),
                w + (size_t)(b0 + tid) * DDIM, DDIM * 4, mbar);
    } else if (tid < BB + RDIM) {
        int r = tid - BB;
        bulk_cp(smem_u32(e_s + r * ROWF),
                e + (size_t)r * DDIM, DDIM * 4, mbar);
    }
    mbar_wait(mbar, 0);

    // ---- HMMA main loop: warp (mh, nq) computes 16 rows x 16 cols ----
    // K-permutation trick: thread kk consumes the contiguous float4 at
    // 16*blk + 4*kk for BOTH A and B. Dot products are invariant to the
    // K->(kstep, lane-slot) assignment as long as A and B agree.
    const int mh = wid >> 2;          // 0..1  (M half)
    const int nq = wid & 3;           // 0..3  (N quarter)
    const int gi = lane >> 2;         // 0..7
    const int kk = lane & 3;          // 0..3
    const int r_lo = 16 * mh + gi;

    const float4* wlo4 = reinterpret_cast<const float4*>(w_s + r_lo * ROWF) + kk;
    const float4* whi4 = reinterpret_cast<const float4*>(w_s + (r_lo + 8) * ROWF) + kk;
    const float4* eb04 = reinterpret_cast<const float4*>(e_s + (16 * nq + gi) * ROWF) + kk;
    const float4* eb14 = reinterpret_cast<const float4*>(e_s + (16 * nq + gi + 8) * ROWF) + kk;

    float acc[2][3][4];               // [n-tile][term hh/hl/lh][4]
#pragma unroll
    for (int t = 0; t < 2; t++)
#pragma unroll
        for (int q = 0; q < 3; q++)
#pragma unroll
            for (int i = 0; i < 4; i++) acc[t][q][i] = 0.f;

#pragma unroll 4
    for (int blk = 0; blk < DDIM / 16; blk++) {
        const int o = 4 * blk;
        float4 wl = wlo4[o];          // row gi     (elems 16blk+4kk .. +3)
        float4 wh = whi4[o];          // row gi+8
        float4 e0 = eb04[o];          // n-tile 0 col
        float4 e1 = eb14[o];          // n-tile 1 col

        // kstep 0 uses (.x, .y) as (v=kk, v=kk+4); kstep 1 uses (.z, .w)
        uint32_t ah0[4], al0[4], ah1[4], al1[4];
        split_u(wl.x, ah0[0], al0[0]);  split_u(wh.x, ah0[1], al0[1]);
        split_u(wl.y, ah0[2], al0[2]);  split_u(wh.y, ah0[3], al0[3]);
        split_u(wl.z, ah1[0], al1[0]);  split_u(wh.z, ah1[1], al1[1]);
        split_u(wl.w, ah1[2], al1[2]);  split_u(wh.w, ah1[3], al1[3]);

        uint32_t e0xh, e0xl, e0yh, e0yl, e0zh, e0zl, e0wh, e0wl;
        uint32_t e1xh, e1xl, e1yh, e1yl, e1zh, e1zl, e1wh, e1wl;
        split_u(e0.x, e0xh, e0xl); split_u(e0.y, e0yh, e0yl);
        split_u(e0.z, e0zh, e0zl); split_u(e0.w, e0wh, e0wl);
        split_u(e1.x, e1xh, e1xl); split_u(e1.y, e1yh, e1yl);
        split_u(e1.z, e1zh, e1zl); split_u(e1.w, e1wh, e1wl);

        // kstep 0
        mma_tf32(acc[0][0], ah0, e0xh, e0yh);
        mma_tf32(acc[0][1], ah0, e0xl, e0yl);
        mma_tf32(acc[0][2], al0, e0xh, e0yh);
        mma_tf32(acc[1][0], ah0, e1xh, e1yh);
        mma_tf32(acc[1][1], ah0, e1xl, e1yl);
        mma_tf32(acc[1][2], al0, e1xh, e1yh);
        // kstep 1
        mma_tf32(acc[0][0], ah1, e0zh, e0wh);
        mma_tf32(acc[0][1], ah1, e0zl, e0wl);
        mma_tf32(acc[0][2], al1, e0zh, e0wh);
        mma_tf32(acc[1][0], ah1, e1zh, e1wh);
        mma_tf32(acc[1][1], ah1, e1zl, e1wl);
        mma_tf32(acc[1][2], al1, e1zh, e1wh);
    }

    // ---- write dot products to s_s[b][r] (verified mapping from R7) ----
#pragma unroll
    for (int t = 0; t < 2; t++) {
        const int cb = 16 * nq + 8 * t + 2 * kk;
        s_s[r_lo][cb]         = (acc[t][0][0] + acc[t][1][0]) + acc[t][2][0];
        s_s[r_lo][cb + 1]     = (acc[t][0][1] + acc[t][1][1]) + acc[t][2][1];
        s_s[r_lo + 8][cb]     = (acc[t][0][2] + acc[t][1][2]) + acc[t][2][2];
        s_s[r_lo + 8][cb + 1] = (acc[t][0][3] + acc[t][1][3]) + acc[t][2][3];
    }

    // ---- norms from smem ----
    {   // ||e_r||^2: r = tid>>2 (0..63), slice = tid&3 (32 float4)
        const int r = tid >> 2, sl = tid & 3;
        const float4* p = reinterpret_cast<const float4*>(e_s + r * ROWF) + sl * 32;
        float a = 0.f;
#pragma unroll 8
        for (int k = 0; k < 32; k++) {
            float4 v = p[k];
            a = fmaf(v.x, v.x, a); a = fmaf(v.y, v.y, a);
            a = fmaf(v.z, v.z, a); a = fmaf(v.w, v.w, a);
        }
        ne_red[r][sl] = a;
    }
    {   // ||w_b||^2: bl = tid>>3 (0..31), slice = tid&7 (16 float4)
        const int bl = tid >> 3, sl = tid & 7;
        const float4* p = reinterpret_cast<const float4*>(w_s + bl * ROWF) + sl * 16;
        float a = 0.f;
#pragma unroll 4
        for (int k = 0; k < 16; k++) {
            float4 v = p[k];
            a = fmaf(v.x, v.x, a); a = fmaf(v.y, v.y, a);
            a = fmaf(v.z, v.z, a); a = fmaf(v.w, v.w, a);
        }
        nw_red[bl][sl] = a;
    }
    __syncthreads();
    if (tid < RDIM)
        ne_s[tid] = ne_red[tid][0] + ne_red[tid][1] + ne_red[tid][2] + ne_red[tid][3];
    __syncthreads();

    // ---- per-row epilogue: thread tid < 32 owns row b0+tid ----
    if (tid < BB) {
        const int r = tid;
        int y = 0;
        {
            const float4* lp = reinterpret_cast<const float4*>(
                label + (size_t)(b0 + r) * RDIM);
            float lm = -1e30f;
#pragma unroll
            for (int g = 0; g < 16; g++) {
                float4 v = lp[g];
                if (v.x > lm) { lm = v.x; y = g * 4; }
                if (v.y > lm) { lm = v.y; y = g * 4 + 1; }
                if (v.z > lm) { lm = v.z; y = g * 4 + 2; }
                if (v.w > lm) { lm = v.w; y = g * 4 + 3; }
            }
        }
        float m1 = -1e30f, m2 = -1e30f, s_y = 0.f;
        int i1 = 0;
#pragma unroll
        for (int c = 0; c < RDIM; c++) {
            float sv = fmaf(-2.f, s_s[r][c], ne_s[c]);
            if (c == y) s_y = sv;
            if (sv > m1)      { m2 = m1; m1 = sv; i1 = c; }
            else if (sv > m2) { m2 = sv; }
        }
        float nw = 0.f;
#pragma unroll
        for (int k = 0; k < 8; k++) nw += nw_red[r][k];

        float plus2  = fmaxf(nw + s_y, 0.f);
        float minus2 = fmaxf(nw + ((i1 == y) ? m2 : m1), 0.f);
        float loss_b = 1.f + sqrtf(plus2) - sqrtf(minus2);
        idx1_s[r] = i1;
#pragma unroll
        for (int off = 16; off; off >>= 1)
            loss_b += __shfl_xor_sync(0xFFFFFFFFu, loss_b, off);
        if (lane == 0) g_partial[blockIdx.x] = loss_b;
    }
    __syncthreads();

    // ---- coalesced one-hot pred write (2 float4 per thread) ----
    {
        float4* op = reinterpret_cast<float4*>(out + (size_t)b0 * RDIM);
#pragma unroll
        for (int k = 0; k < 2; k++) {
            int i  = tid * 8 + k * 4;
            int bl = i >> 6;
            int r  = i & 63;
            int p  = idx1_s[bl];
            float4 v;
            v.x = (r + 0 == p) ? 1.f : 0.f;
            v.y = (r + 1 == p) ? 1.f : 0.f;
            v.z = (r + 2 == p) ? 1.f : 0.f;
            v.w = (r + 3 == p) ? 1.f : 0.f;
            op[tid * 2 + k] = v;
        }
    }

    // ---- fused finalize: last block reduces g_partial deterministically ----
    if (tid == 0) {
        __threadfence();
        int c = atomicAdd(&g_count, 1);
        is_last = (c == gridDim.x - 1) ? 1 : 0;
    }
    __syncthreads();
    if (is_last) {
        __threadfence();
        if (tid < NBLOCK) fs[tid] = g_partial[tid];
        __syncthreads();
#pragma unroll
        for (int off = NBLOCK / 2; off > 0; off >>= 1) {
            if (tid < off) fs[tid] += fs[tid + off];
            __syncthreads();
        }
        if (tid == 0) {
            out[out_size - 1] = fs[0] * (1.0f / (float)BDIM);
            g_count = 0;
        }
    }
}

extern "C" void kernel_launch(void* const* d_in, const int* in_sizes, int n_in,
                              void* d_out, int out_size)
{
    const float* w     = (const float*)d_in[0];   // [4096, 512]
    const float* e     = (const float*)d_in[1];   // [64, 512]
    const float* label = (const float*)d_in[2];   // [4096, 64]
    float* out = (float*)d_out;                   // pred [4096*64] ++ loss [1]

    cudaFuncSetAttribute(fused_kernel,
                         cudaFuncAttributeMaxDynamicSharedMemorySize, DYN_SMEM);
    fused_kernel<<<NBLOCK, NTHREADS, DYN_SMEM>>>(w, e, label, out, out_size);
}

// round 12
// speedup vs baseline: 1.0952x; 1.0952x over previous
#include <cuda_runtime.h>
#include <math.h>
#include <stdint.h>

#define BDIM 4096
#define RDIM 64
#define DDIM 512
#define BB   32
#define NBLOCK (BDIM / BB)      // 128 CTAs
#define NTHREADS 256
#define KQ   128                // K per quarter
#define ROWFL 144               // floats per padded row (36 float4; 36 mod 8 == 4)
#define BUF_F (192 * ROWFL)     // w_hi(32)+w_lo(32)+e_hi(64)+e_lo(64) rows = 27648 floats
#define DYN_SMEM (2 * BUF_F * 4)   // 221184 B

#define WLO_F (32 * ROWFL)
#define EHI_F (64 * ROWFL)
#define ELO_F (128 * ROWFL)

__device__ float g_partial[NBLOCK];
__device__ int   g_count = 0;

__device__ __forceinline__ uint32_t smem_u32(const void* p) {
    return (uint32_t)__cvta_generic_to_shared(p);
}
__device__ __forceinline__ void bulk_cp(uint32_t dst, const void* src,
                                        uint32_t bytes, uint32_t mbar) {
    asm volatile(
        "cp.async.bulk.shared::cta.global.mbarrier::complete_tx::bytes [%0], [%1], %2, [%3];"
        :: "r"(dst), "l"(src), "r"(bytes), "r"(mbar) : "memory");
}
__device__ __forceinline__ void mbar_init(uint32_t mbar, uint32_t cnt) {
    asm volatile("mbarrier.init.shared.b64 [%0], %1;" :: "r"(mbar), "r"(cnt) : "memory");
}
__device__ __forceinline__ void mbar_expect_tx(uint32_t mbar, uint32_t bytes) {
    asm volatile("mbarrier.arrive.expect_tx.shared.b64 _, [%0], %1;"
                 :: "r"(mbar), "r"(bytes) : "memory");
}
__device__ __forceinline__ void mbar_wait(uint32_t mbar, uint32_t parity) {
    asm volatile(
        "{\n\t.reg .pred P;\n\t"
        "WL_%=:\n\t"
        "mbarrier.try_wait.parity.acquire.cta.shared::cta.b64 P, [%0], %1, 0x989680;\n\t"
        "@P bra.uni WD_%=;\n\t"
        "bra.uni WL_%=;\n\t"
        "WD_%=:\n\t}"
        :: "r"(mbar), "r"(parity) : "memory");
}
__device__ __forceinline__ void split1(float x, float& h, float& l) {
    h = __uint_as_float(__float_as_uint(x) & 0xFFFFE000u);
    l = x - h;
}
__device__ __forceinline__ void split4(float4 v, float4& h, float4& l) {
    split1(v.x, h.x, l.x); split1(v.y, h.y, l.y);
    split1(v.z, h.z, l.z); split1(v.w, h.w, l.w);
}
__device__ __forceinline__ void mma_tf32(float* c, const uint32_t* a,
                                         uint32_t b0, uint32_t b1) {
    asm volatile(
        "mma.sync.aligned.m16n8k8.row.col.f32.tf32.tf32.f32 "
        "{%0,%1,%2,%3}, {%4,%5,%6,%7}, {%8,%9}, {%0,%1,%2,%3};"
        : "+f"(c[0]), "+f"(c[1]), "+f"(c[2]), "+f"(c[3])
        : "r"(a[0]), "r"(a[1]), "r"(a[2]), "r"(a[3]), "r"(b0), "r"(b1));
}

__global__ __launch_bounds__(NTHREADS, 1)
void fused_kernel(const float* __restrict__ w,
                  const float* __restrict__ e,
                  const float* __restrict__ label,
                  float* __restrict__ out, int out_size)
{
    extern __shared__ __align__(16) float dyn[];

    __shared__ __align__(8) uint64_t mbar_sto[4];
    __shared__ float ne_red[RDIM][4];
    __shared__ float ne_s[RDIM];
    __shared__ float nw_red[BB][9];
    __shared__ int   idx1_s[BB];
    __shared__ float fs[NBLOCK];
    __shared__ int   is_last;

    const int tid  = threadIdx.x;
    const int lane = tid & 31;
    const int wid  = tid >> 5;
    const int b0   = blockIdx.x * BB;

    // s_s aliases buffer 0 (dead after mma of quarter 2)
    float (*s_s)[65] = reinterpret_cast<float (*)[65]>(dyn);

    uint32_t mbars[4];
#pragma unroll
    for (int q = 0; q < 4; q++) mbars[q] = smem_u32(&mbar_sto[q]);

    // ---- mbarrier setup + prologue staging (quarters 0 and 1) ----
    if (tid == 0) {
#pragma unroll
        for (int q = 0; q < 4; q++) mbar_init(mbars[q], 1);
    }
    __syncthreads();
    if (tid == 0) {
#pragma unroll
        for (int q = 0; q < 4; q++) mbar_expect_tx(mbars[q], 96 * KQ * 4);
    }
    __syncthreads();

    auto issue_quarter = [&](int q) {
        int base = (q & 1) ? 96 : 0;
        int t = tid - base;
        if (t >= 0 && t < 96) {
            float* B = dyn + (q & 1) * BUF_F;
            if (t < 32)
                bulk_cp(smem_u32(B + t * ROWFL),
                        w + (size_t)(b0 + t) * DDIM + q * KQ, KQ * 4, mbars[q]);
            else {
                int r = t - 32;
                bulk_cp(smem_u32(B + EHI_F + r * ROWFL),
                        e + (size_t)r * DDIM + q * KQ, KQ * 4, mbars[q]);
            }
        }
    };
    issue_quarter(0);
    issue_quarter(1);

    // warp tile (verified R7 mapping): (mh, nq) -> 16 rows x 16 cols
    const int mh = wid >> 2;
    const int nq = wid & 3;
    const int gi = lane >> 2;
    const int kk = lane & 3;
    const int r_lo = 16 * mh + gi;

    // split-pass thread mapping (diagonal k-columns -> conflict-free STS.128)
    const int w_row = tid >> 3, w_c = tid & 7;     // w: 8 threads/row, 4 f4 each
    const int e_row = tid >> 2, e_c = tid & 3;     // e: 4 threads/row, 8 f4 each

    float acc[2][3][4];               // [n-tile][term hh/hl/lh][4]
#pragma unroll
    for (int t = 0; t < 2; t++)
#pragma unroll
        for (int q = 0; q < 3; q++)
#pragma unroll
            for (int i = 0; i < 4; i++) acc[t][q][i] = 0.f;

    float nw_acc = 0.f, ne_acc = 0.f;

    for (int q = 0; q < 4; q++) {
        float* B = dyn + (q & 1) * BUF_F;
        mbar_wait(mbars[q], 0);

        // ---- split pass: raw(hi area) -> hi in place + lo; norms ride along ----
        {
            float4* wr = reinterpret_cast<float4*>(B + w_row * ROWFL);
            float4* wl = reinterpret_cast<float4*>(B + WLO_F + w_row * ROWFL);
#pragma unroll
            for (int j = 0; j < 4; j++) {
                int k4 = w_c + 8 * j;
                float4 v = wr[k4];
                float4 h, l; split4(v, h, l);
                wr[k4] = h; wl[k4] = l;
                nw_acc = fmaf(v.x, v.x, nw_acc); nw_acc = fmaf(v.y, v.y, nw_acc);
                nw_acc = fmaf(v.z, v.z, nw_acc); nw_acc = fmaf(v.w, v.w, nw_acc);
            }
            float4* er = reinterpret_cast<float4*>(B + EHI_F + e_row * ROWFL);
            float4* el = reinterpret_cast<float4*>(B + ELO_F + e_row * ROWFL);
#pragma unroll
            for (int j = 0; j < 8; j++) {
                int k4 = e_c + 4 * j;
                float4 v = er[k4];
                float4 h, l; split4(v, h, l);
                er[k4] = h; el[k4] = l;
                ne_acc = fmaf(v.x, v.x, ne_acc); ne_acc = fmaf(v.y, v.y, ne_acc);
                ne_acc = fmaf(v.z, v.z, ne_acc); ne_acc = fmaf(v.w, v.w, ne_acc);
            }
        }
        __syncthreads();   // splits visible; all warps done mma(q-1)

        if (q >= 1 && q <= 2) issue_quarter(q + 1);   // overlaps with mma(q)

        // ---- pure LDS + HMMA over this quarter's 8 blocks ----
        const float4* wlh = reinterpret_cast<const float4*>(B) + r_lo * 36;
        const float4* whh = wlh + 8 * 36;
        const float4* wll = reinterpret_cast<const float4*>(B + WLO_F) + r_lo * 36;
        const float4* whl = wll + 8 * 36;
        const float4* e0h = reinterpret_cast<const float4*>(B + EHI_F) + (16 * nq + gi) * 36;
        const float4* e1h = e0h + 8 * 36;
        const float4* e0l = reinterpret_cast<const float4*>(B + ELO_F) + (16 * nq + gi) * 36;
        const float4* e1l = e0l + 8 * 36;

#pragma unroll
        for (int blk = 0; blk < KQ / 16; blk++) {
            const int o = 4 * blk + kk;
            float4 WLh = wlh[o], WHh = whh[o], WLl = wll[o], WHl = whl[o];
            float4 E0h = e0h[o], E0l = e0l[o], E1h = e1h[o], E1l = e1l[o];

            uint32_t ah0[4] = {__float_as_uint(WLh.x), __float_as_uint(WHh.x),
                               __float_as_uint(WLh.y), __float_as_uint(WHh.y)};
            uint32_t al0[4] = {__float_as_uint(WLl.x), __float_as_uint(WHl.x),
                               __float_as_uint(WLl.y), __float_as_uint(WHl.y)};
            uint32_t ah1[4] = {__float_as_uint(WLh.z), __float_as_uint(WHh.z),
                               __float_as_uint(WLh.w), __float_as_uint(WHh.w)};
            uint32_t al1[4] = {__float_as_uint(WLl.z), __float_as_uint(WHl.z),
                               __float_as_uint(WLl.w), __float_as_uint(WHl.w)};

            // kstep 0: (.x, .y)
            mma_tf32(acc[0][0], ah0, __float_as_uint(E0h.x), __float_as_uint(E0h.y));
            mma_tf32(acc[0][1], ah0, __float_as_uint(E0l.x), __float_as_uint(E0l.y));
            mma_tf32(acc[0][2], al0, __float_as_uint(E0h.x), __float_as_uint(E0h.y));
            mma_tf32(acc[1][0], ah0, __float_as_uint(E1h.x), __float_as_uint(E1h.y));
            mma_tf32(acc[1][1], ah0, __float_as_uint(E1l.x), __float_as_uint(E1l.y));
            mma_tf32(acc[1][2], al0, __float_as_uint(E1h.x), __float_as_uint(E1h.y));
            // kstep 1: (.z, .w)
            mma_tf32(acc[0][0], ah1, __float_as_uint(E0h.z), __float_as_uint(E0h.w));
            mma_tf32(acc[0][1], ah1, __float_as_uint(E0l.z), __float_as_uint(E0l.w));
            mma_tf32(acc[0][2], al1, __float_as_uint(E0h.z), __float_as_uint(E0h.w));
            mma_tf32(acc[1][0], ah1, __float_as_uint(E1h.z), __float_as_uint(E1h.w));
            mma_tf32(acc[1][1], ah1, __float_as_uint(E1l.z), __float_as_uint(E1l.w));
            mma_tf32(acc[1][2], al1, __float_as_uint(E1h.z), __float_as_uint(E1h.w));
        }
    }

    // ---- write dot products to s_s[b][r] (aliases dead buf0) ----
#pragma unroll
    for (int t = 0; t < 2; t++) {
        const int cb = 16 * nq + 8 * t + 2 * kk;
        s_s[r_lo][cb]         = (acc[t][0][0] + acc[t][1][0]) + acc[t][2][0];
        s_s[r_lo][cb + 1]     = (acc[t][0][1] + acc[t][1][1]) + acc[t][2][1];
        s_s[r_lo + 8][cb]     = (acc[t][0][2] + acc[t][1][2]) + acc[t][2][2];
        s_s[r_lo + 8][cb + 1] = (acc[t][0][3] + acc[t][1][3]) + acc[t][2][3];
    }
    nw_red[w_row][w_c] = nw_acc;
    ne_red[e_row][e_c] = ne_acc;
    __syncthreads();
    if (tid < RDIM)
        ne_s[tid] = ne_red[tid][0] + ne_red[tid][1] + ne_red[tid][2] + ne_red[tid][3];
    __syncthreads();

    // ---- per-row epilogue: thread tid < 32 owns row b0+tid ----
    if (tid < BB) {
        const int r = tid;
        int y = 0;
        {
            const float4* lp = reinterpret_cast<const float4*>(
                label + (size_t)(b0 + r) * RDIM);
            float lm = -1e30f;
#pragma unroll
            for (int g = 0; g < 16; g++) {
                float4 v = lp[g];
                if (v.x > lm) { lm = v.x; y = g * 4; }
                if (v.y > lm) { lm = v.y; y = g * 4 + 1; }
                if (v.z > lm) { lm = v.z; y = g * 4 + 2; }
                if (v.w > lm) { lm = v.w; y = g * 4 + 3; }
            }
        }
        float m1 = -1e30f, m2 = -1e30f, s_y = 0.f;
        int i1 = 0;
#pragma unroll
        for (int c = 0; c < RDIM; c++) {
            float sv = fmaf(-2.f, s_s[r][c], ne_s[c]);
            if (c == y) s_y = sv;
            if (sv > m1)      { m2 = m1; m1 = sv; i1 = c; }
            else if (sv > m2) { m2 = sv; }
        }
        float nw = 0.f;
#pragma unroll
        for (int k = 0; k < 8; k++) nw += nw_red[r][k];

        float plus2  = fmaxf(nw + s_y, 0.f);
        float minus2 = fmaxf(nw + ((i1 == y) ? m2 : m1), 0.f);
        float loss_b = 1.f + sqrtf(plus2) - sqrtf(minus2);
        idx1_s[r] = i1;
#pragma unroll
        for (int off = 16; off; off >>= 1)
            loss_b += __shfl_xor_sync(0xFFFFFFFFu, loss_b, off);
        if (lane == 0) g_partial[blockIdx.x] = loss_b;
    }
    __syncthreads();

    // ---- coalesced one-hot pred write (2 float4 per thread) ----
    {
        float4* op = reinterpret_cast<float4*>(out + (size_t)b0 * RDIM);
#pragma unroll
        for (int k = 0; k < 2; k++) {
            int i  = tid * 8 + k * 4;
            int bl = i >> 6;
            int r  = i & 63;
            int p  = idx1_s[bl];
            float4 v;
            v.x = (r + 0 == p) ? 1.f : 0.f;
            v.y = (r + 1 == p) ? 1.f : 0.f;
            v.z = (r + 2 == p) ? 1.f : 0.f;
            v.w = (r + 3 == p) ? 1.f : 0.f;
            op[tid * 2 + k] = v;
        }
    }

    // ---- fused finalize: last block reduces g_partial deterministically ----
    if (tid == 0) {
        __threadfence();
        int c = atomicAdd(&g_count, 1);
        is_last = (c == gridDim.x - 1) ? 1 : 0;
    }
    __syncthreads();
    if (is_last) {
        __threadfence();
        if (tid < NBLOCK) fs[tid] = g_partial[tid];
        __syncthreads();
#pragma unroll
        for (int off = NBLOCK / 2; off > 0; off >>= 1) {
            if (tid < off) fs[tid] += fs[tid + off];
            __syncthreads();
        }
        if (tid == 0) {
            out[out_size - 1] = fs[0] * (1.0f / (float)BDIM);
            g_count = 0;
        }
    }
}

extern "C" void kernel_launch(void* const* d_in, const int* in_sizes, int n_in,
                              void* d_out, int out_size)
{
    const float* w     = (const float*)d_in[0];   // [4096, 512]
    const float* e     = (const float*)d_in[1];   // [64, 512]
    const float* label = (const float*)d_in[2];   // [4096, 64]
    float* out = (float*)d_out;                   // pred [4096*64] ++ loss [1]

    cudaFuncSetAttribute(fused_kernel,
                         cudaFuncAttributeMaxDynamicSharedMemorySize, DYN_SMEM);
    fused_kernel<<<NBLOCK, NTHREADS, DYN_SMEM>>>(w, e, label, out, out_size);
}

// round 13
// speedup vs baseline: 1.1081x; 1.0118x over previous
#include <cuda_runtime.h>
#include <math.h>
#include <stdint.h>

#define BDIM 4096
#define RDIM 64
#define DDIM 512
#define BB   32
#define NBLOCK (BDIM / BB)      // 128 CTAs
#define NTHREADS 512
#define KQ   128                // K per quarter
#define ROWFL 144               // floats per padded row (36 float4; 36 mod 8 == 4)
#define BUF_F (192 * ROWFL)     // w_hi(32)+w_lo(32)+e_hi(64)+e_lo(64) rows
#define DYN_SMEM (2 * BUF_F * 4)   // 221184 B

#define WLO_F (32 * ROWFL)
#define EHI_F (64 * ROWFL)
#define ELO_F (128 * ROWFL)

__device__ float g_partial[NBLOCK];
__device__ int   g_count = 0;

__device__ __forceinline__ uint32_t smem_u32(const void* p) {
    return (uint32_t)__cvta_generic_to_shared(p);
}
__device__ __forceinline__ void bulk_cp(uint32_t dst, const void* src,
                                        uint32_t bytes, uint32_t mbar) {
    asm volatile(
        "cp.async.bulk.shared::cta.global.mbarrier::complete_tx::bytes [%0], [%1], %2, [%3];"
        :: "r"(dst), "l"(src), "r"(bytes), "r"(mbar) : "memory");
}
__device__ __forceinline__ void mbar_init(uint32_t mbar, uint32_t cnt) {
    asm volatile("mbarrier.init.shared.b64 [%0], %1;" :: "r"(mbar), "r"(cnt) : "memory");
}
__device__ __forceinline__ void mbar_expect_tx(uint32_t mbar, uint32_t bytes) {
    asm volatile("mbarrier.arrive.expect_tx.shared.b64 _, [%0], %1;"
                 :: "r"(mbar), "r"(bytes) : "memory");
}
__device__ __forceinline__ void mbar_wait(uint32_t mbar, uint32_t parity) {
    asm volatile(
        "{\n\t.reg .pred P;\n\t"
        "WL_%=:\n\t"
        "mbarrier.try_wait.parity.acquire.cta.shared::cta.b64 P, [%0], %1, 0x989680;\n\t"
        "@P bra.uni WD_%=;\n\t"
        "bra.uni WL_%=;\n\t"
        "WD_%=:\n\t}"
        :: "r"(mbar), "r"(parity) : "memory");
}
__device__ __forceinline__ void split1(float x, float& h, float& l) {
    h = __uint_as_float(__float_as_uint(x) & 0xFFFFE000u);
    l = x - h;
}
__device__ __forceinline__ void split4(float4 v, float4& h, float4& l) {
    split1(v.x, h.x, l.x); split1(v.y, h.y, l.y);
    split1(v.z, h.z, l.z); split1(v.w, h.w, l.w);
}
__device__ __forceinline__ void mma_tf32(float* c, const uint32_t* a,
                                         uint32_t b0, uint32_t b1) {
    asm volatile(
        "mma.sync.aligned.m16n8k8.row.col.f32.tf32.tf32.f32 "
        "{%0,%1,%2,%3}, {%4,%5,%6,%7}, {%8,%9}, {%0,%1,%2,%3};"
        : "+f"(c[0]), "+f"(c[1]), "+f"(c[2]), "+f"(c[3])
        : "r"(a[0]), "r"(a[1]), "r"(a[2]), "r"(a[3]), "r"(b0), "r"(b1));
}

__global__ __launch_bounds__(NTHREADS, 1)
void fused_kernel(const float* __restrict__ w,
                  const float* __restrict__ e,
                  const float* __restrict__ label,
                  float* __restrict__ out, int out_size)
{
    extern __shared__ __align__(16) float dyn[];

    __shared__ __align__(8) uint64_t mbar_sto[4];
    __shared__ float ne_red[RDIM][9];
    __shared__ float ne_s[RDIM];
    __shared__ float nw_red[BB][17];
    __shared__ int   idx1_s[BB];
    __shared__ float fs[NBLOCK];
    __shared__ int   is_last;

    const int tid  = threadIdx.x;
    const int lane = tid & 31;
    const int wid  = tid >> 5;
    const int b0   = blockIdx.x * BB;

    // s_s aliases buffer 0 (dead after quarter 2's MMAs)
    float (*s_s)[65] = reinterpret_cast<float (*)[65]>(dyn);

    uint32_t mbars[4];
#pragma unroll
    for (int q = 0; q < 4; q++) mbars[q] = smem_u32(&mbar_sto[q]);

    if (tid == 0) {
#pragma unroll
        for (int q = 0; q < 4; q++) mbar_init(mbars[q], 1);
    }
    __syncthreads();
    if (tid == 0) {
#pragma unroll
        for (int q = 0; q < 4; q++) mbar_expect_tx(mbars[q], 96 * KQ * 4);
    }
    __syncthreads();

    auto issue_quarter = [&](int q) {
        int base = (q & 1) ? 96 : 0;
        int t = tid - base;
        if (t >= 0 && t < 96) {
            float* B = dyn + (q & 1) * BUF_F;
            if (t < 32)
                bulk_cp(smem_u32(B + t * ROWFL),
                        w + (size_t)(b0 + t) * DDIM + q * KQ, KQ * 4, mbars[q]);
            else {
                int r = t - 32;
                bulk_cp(smem_u32(B + EHI_F + r * ROWFL),
                        e + (size_t)r * DDIM + q * KQ, KQ * 4, mbars[q]);
            }
        }
    };
    issue_quarter(0);
    issue_quarter(1);

    // warp tile: (kh, mh, nq) -> warp pair shares a 16x16 tile, split by k-blocks
    const int kh = wid >> 3;          // 0..1  (k-block half within quarter)
    const int mh = (wid >> 2) & 1;    // 0..1
    const int nq = wid & 3;           // 0..3
    const int gi = lane >> 2;
    const int kk = lane & 3;
    const int r_lo = 16 * mh + gi;

    // split-pass mapping for 512 threads (conflict-free, checked mod-8)
    const int w_row = tid >> 4, w_c = tid & 15;    // 16 thr/row, 2 f4 each
    const int e_row = tid >> 3, e_c = tid & 7;     // 8 thr/row, 4 f4 each

    float acc[2][3][4];               // [n-tile][term hh/hl/lh][4]
#pragma unroll
    for (int t = 0; t < 2; t++)
#pragma unroll
        for (int q = 0; q < 3; q++)
#pragma unroll
            for (int i = 0; i < 4; i++) acc[t][q][i] = 0.f;

    float nw_acc = 0.f, ne_acc = 0.f;

    for (int q = 0; q < 4; q++) {
        float* B = dyn + (q & 1) * BUF_F;
        mbar_wait(mbars[q], 0);

        // ---- split pass (512 threads): raw -> hi in place + lo; norms ride along ----
        {
            float4* wr = reinterpret_cast<float4*>(B + w_row * ROWFL);
            float4* wl = reinterpret_cast<float4*>(B + WLO_F + w_row * ROWFL);
#pragma unroll
            for (int j = 0; j < 2; j++) {
                int k4 = w_c + 16 * j;
                float4 v = wr[k4];
                float4 h, l; split4(v, h, l);
                wr[k4] = h; wl[k4] = l;
                nw_acc = fmaf(v.x, v.x, nw_acc); nw_acc = fmaf(v.y, v.y, nw_acc);
                nw_acc = fmaf(v.z, v.z, nw_acc); nw_acc = fmaf(v.w, v.w, nw_acc);
            }
            float4* er = reinterpret_cast<float4*>(B + EHI_F + e_row * ROWFL);
            float4* el = reinterpret_cast<float4*>(B + ELO_F + e_row * ROWFL);
#pragma unroll
            for (int j = 0; j < 4; j++) {
                int k4 = e_c + 8 * j;
                float4 v = er[k4];
                float4 h, l; split4(v, h, l);
                er[k4] = h; el[k4] = l;
                ne_acc = fmaf(v.x, v.x, ne_acc); ne_acc = fmaf(v.y, v.y, ne_acc);
                ne_acc = fmaf(v.z, v.z, ne_acc); ne_acc = fmaf(v.w, v.w, ne_acc);
            }
        }
        __syncthreads();   // splits visible; all warps done with previous MMAs

        if (q >= 1 && q <= 2) issue_quarter(q + 1);   // overlaps with mma(q)

        // ---- pure LDS + HMMA: this warp's 4 of the quarter's 8 blocks ----
        const float4* wlh = reinterpret_cast<const float4*>(B) + r_lo * 36;
        const float4* whh = wlh + 8 * 36;
        const float4* wll = reinterpret_cast<const float4*>(B + WLO_F) + r_lo * 36;
        const float4* whl = wll + 8 * 36;
        const float4* e0h = reinterpret_cast<const float4*>(B + EHI_F) + (16 * nq + gi) * 36;
        const float4* e1h = e0h + 8 * 36;
        const float4* e0l = reinterpret_cast<const float4*>(B + ELO_F) + (16 * nq + gi) * 36;
        const float4* e1l = e0l + 8 * 36;

#pragma unroll
        for (int blk = 0; blk < 4; blk++) {
            const int o = 4 * (kh * 4 + blk) + kk;
            float4 WLh = wlh[o], WHh = whh[o], WLl = wll[o], WHl = whl[o];
            float4 E0h = e0h[o], E0l = e0l[o], E1h = e1h[o], E1l = e1l[o];

            uint32_t ah0[4] = {__float_as_uint(WLh.x), __float_as_uint(WHh.x),
                               __float_as_uint(WLh.y), __float_as_uint(WHh.y)};
            uint32_t al0[4] = {__float_as_uint(WLl.x), __float_as_uint(WHl.x),
                               __float_as_uint(WLl.y), __float_as_uint(WHl.y)};
            uint32_t ah1[4] = {__float_as_uint(WLh.z), __float_as_uint(WHh.z),
                               __float_as_uint(WLh.w), __float_as_uint(WHh.w)};
            uint32_t al1[4] = {__float_as_uint(WLl.z), __float_as_uint(WHl.z),
                               __float_as_uint(WLl.w), __float_as_uint(WHl.w)};

            mma_tf32(acc[0][0], ah0, __float_as_uint(E0h.x), __float_as_uint(E0h.y));
            mma_tf32(acc[0][1], ah0, __float_as_uint(E0l.x), __float_as_uint(E0l.y));
            mma_tf32(acc[0][2], al0, __float_as_uint(E0h.x), __float_as_uint(E0h.y));
            mma_tf32(acc[1][0], ah0, __float_as_uint(E1h.x), __float_as_uint(E1h.y));
            mma_tf32(acc[1][1], ah0, __float_as_uint(E1l.x), __float_as_uint(E1l.y));
            mma_tf32(acc[1][2], al0, __float_as_uint(E1h.x), __float_as_uint(E1h.y));
            mma_tf32(acc[0][0], ah1, __float_as_uint(E0h.z), __float_as_uint(E0h.w));
            mma_tf32(acc[0][1], ah1, __float_as_uint(E0l.z), __float_as_uint(E0l.w));
            mma_tf32(acc[0][2], al1, __float_as_uint(E0h.z), __float_as_uint(E0h.w));
            mma_tf32(acc[1][0], ah1, __float_as_uint(E1h.z), __float_as_uint(E1h.w));
            mma_tf32(acc[1][1], ah1, __float_as_uint(E1l.z), __float_as_uint(E1l.w));
            mma_tf32(acc[1][2], al1, __float_as_uint(E1h.z), __float_as_uint(E1h.w));
        }
    }

    // ---- combine terms, then two-phase deterministic kh merge into s_s ----
    float part[2][4];
#pragma unroll
    for (int t = 0; t < 2; t++)
#pragma unroll
        for (int i = 0; i < 4; i++)
            part[t][i] = (acc[t][0][i] + acc[t][1][i]) + acc[t][2][i];

    __syncthreads();           // all MMAs done; buf0 region (s_s alias) is dead
    if (kh == 0) {
#pragma unroll
        for (int t = 0; t < 2; t++) {
            const int cb = 16 * nq + 8 * t + 2 * kk;
            s_s[r_lo][cb]         = part[t][0];
            s_s[r_lo][cb + 1]     = part[t][1];
            s_s[r_lo + 8][cb]     = part[t][2];
            s_s[r_lo + 8][cb + 1] = part[t][3];
        }
    }
    nw_red[w_row][w_c] = nw_acc;
    ne_red[e_row][e_c] = ne_acc;
    __syncthreads();
    if (kh == 1) {
#pragma unroll
        for (int t = 0; t < 2; t++) {
            const int cb = 16 * nq + 8 * t + 2 * kk;
            s_s[r_lo][cb]         += part[t][0];
            s_s[r_lo][cb + 1]     += part[t][1];
            s_s[r_lo + 8][cb]     += part[t][2];
            s_s[r_lo + 8][cb + 1] += part[t][3];
        }
    }
    if (tid < RDIM) {
        float a = 0.f;
#pragma unroll
        for (int k = 0; k < 8; k++) a += ne_red[tid][k];
        ne_s[tid] = a;
    }
    __syncthreads();

    // ---- per-row epilogue: thread tid < 32 owns row b0+tid ----
    if (tid < BB) {
        const int r = tid;
        int y = 0;
        {
            const float4* lp = reinterpret_cast<const float4*>(
                label + (size_t)(b0 + r) * RDIM);
            float lm = -1e30f;
#pragma unroll
            for (int g = 0; g < 16; g++) {
                float4 v = lp[g];
                if (v.x > lm) { lm = v.x; y = g * 4; }
                if (v.y > lm) { lm = v.y; y = g * 4 + 1; }
                if (v.z > lm) { lm = v.z; y = g * 4 + 2; }
                if (v.w > lm) { lm = v.w; y = g * 4 + 3; }
            }
        }
        float m1 = -1e30f, m2 = -1e30f, s_y = 0.f;
        int i1 = 0;
#pragma unroll
        for (int c = 0; c < RDIM; c++) {
            float sv = fmaf(-2.f, s_s[r][c], ne_s[c]);
            if (c == y) s_y = sv;
            if (sv > m1)      { m2 = m1; m1 = sv; i1 = c; }
            else if (sv > m2) { m2 = sv; }
        }
        float nw = 0.f;
#pragma unroll
        for (int k = 0; k < 16; k++) nw += nw_red[r][k];

        float plus2  = fmaxf(nw + s_y, 0.f);
        float minus2 = fmaxf(nw + ((i1 == y) ? m2 : m1), 0.f);
        float loss_b = 1.f + sqrtf(plus2) - sqrtf(minus2);
        idx1_s[r] = i1;
#pragma unroll
        for (int off = 16; off; off >>= 1)
            loss_b += __shfl_xor_sync(0xFFFFFFFFu, loss_b, off);
        if (lane == 0) g_partial[blockIdx.x] = loss_b;
    }
    __syncthreads();

    // ---- coalesced one-hot pred write (one float4 per thread) ----
    {
        float4* op = reinterpret_cast<float4*>(out + (size_t)b0 * RDIM);
        int bl = tid >> 4;
        int r  = (tid & 15) * 4;
        int p  = idx1_s[bl];
        float4 v;
        v.x = (r + 0 == p) ? 1.f : 0.f;
        v.y = (r + 1 == p) ? 1.f : 0.f;
        v.z = (r + 2 == p) ? 1.f : 0.f;
        v.w = (r + 3 == p) ? 1.f : 0.f;
        op[tid] = v;
    }

    // ---- fused finalize: last block reduces g_partial deterministically ----
    if (tid == 0) {
        __threadfence();
        int c = atomicAdd(&g_count, 1);
        is_last = (c == gridDim.x - 1) ? 1 : 0;
    }
    __syncthreads();
    if (is_last) {
        __threadfence();
        if (tid < NBLOCK) fs[tid] = g_partial[tid];
        __syncthreads();
#pragma unroll
        for (int off = NBLOCK / 2; off > 0; off >>= 1) {
            if (tid < off) fs[tid] += fs[tid + off];
            __syncthreads();
        }
        if (tid == 0) {
            out[out_size - 1] = fs[0] * (1.0f / (float)BDIM);
            g_count = 0;
        }
    }
}

extern "C" void kernel_launch(void* const* d_in, const int* in_sizes, int n_in,
                              void* d_out, int out_size)
{
    const float* w     = (const float*)d_in[0];   // [4096, 512]
    const float* e     = (const float*)d_in[1];   // [64, 512]
    const float* label = (const float*)d_in[2];   // [4096, 64]
    float* out = (float*)d_out;                   // pred [4096*64] ++ loss [1]

    cudaFuncSetAttribute(fused_kernel,
                         cudaFuncAttributeMaxDynamicSharedMemorySize, DYN_SMEM);
    fused_kernel<<<NBLOCK, NTHREADS, DYN_SMEM>>>(w, e, label, out, out_size);
}